// round 15
// baseline (speedup 1.0000x reference)
#include <cuda_runtime.h>
#include <cuda_bf16.h>
#include <cstdint>

#define NTOK 4096
#define KTOP 64
#define DIM  1024
#define NLAT 16384

__device__ __nv_bfloat16 g_Xh[NTOK * DIM];
__device__ __nv_bfloat16 g_Xl[NTOK * DIM];
__device__ __nv_bfloat16 g_Wh[DIM * DIM];
__device__ __nv_bfloat16 g_Wl[DIM * DIM];
__device__ __nv_bfloat16 g_Wdecb[NLAT * DIM];
__device__ float g_colsum_part[64 * DIM];
__device__ float g_s2_part[64 * 4];
__device__ float g_err_part[256];
__device__ int   g_done;          // zero-initialized; reset by finalizer

__device__ __forceinline__ void mma16816(float* d, const uint32_t* a,
                                         const uint32_t* b) {
    asm volatile(
        "mma.sync.aligned.m16n8k16.row.col.f32.bf16.bf16.f32 "
        "{%0,%1,%2,%3}, {%4,%5,%6,%7}, {%8,%9}, {%0,%1,%2,%3};"
        : "+f"(d[0]), "+f"(d[1]), "+f"(d[2]), "+f"(d[3])
        : "r"(a[0]), "r"(a[1]), "r"(a[2]), "r"(a[3]), "r"(b[0]), "r"(b[1]));
}
__device__ __forceinline__ void ldsm4(uint32_t* r, uint32_t addr) {
    asm volatile("ldmatrix.sync.aligned.m8n8.x4.shared.b16 {%0,%1,%2,%3}, [%4];"
                 : "=r"(r[0]), "=r"(r[1]), "=r"(r[2]), "=r"(r[3]) : "r"(addr));
}
__device__ __forceinline__ void ldsm2(uint32_t* r, uint32_t addr) {
    asm volatile("ldmatrix.sync.aligned.m8n8.x2.shared.b16 {%0,%1}, [%2];"
                 : "=r"(r[0]), "=r"(r[1]) : "r"(addr));
}
__device__ __forceinline__ uint32_t smem_to_u32(const void* p) {
    uint32_t a;
    asm("{ .reg .u64 t; cvta.to.shared.u64 t, %1; cvt.u32.u64 %0, t; }"
        : "=r"(a) : "l"(p));
    return a;
}
__device__ __forceinline__ void cp16(uint32_t dst, const void* src) {
    asm volatile("cp.async.cg.shared.global [%0], [%1], 16;"
                 :: "r"(dst), "l"(src) : "memory");
}
#define CP_COMMIT() asm volatile("cp.async.commit_group;" ::: "memory")
#define CP_WAIT3()  asm volatile("cp.async.wait_group 3;" ::: "memory")
#define CP_WAIT0()  asm volatile("cp.async.wait_group 0;" ::: "memory")
#define NBAR(id, cnt) \
    asm volatile("bar.sync %0, %1;" :: "r"(id), "r"(cnt) : "memory")

__device__ __forceinline__ float bf_hi(uint32_t r) {
    return __uint_as_float(r & 0xFFFF0000u);
}
__device__ __forceinline__ float bf_lo(uint32_t r) {
    return __uint_as_float(r << 16);
}

#define XU8  (NTOK * DIM / 8)
#define WU8  (DIM * DIM / 8)
#define WDU8 (NLAT * DIM / 8)

// pack 4 floats -> 2 bf16x2 words
__device__ __forceinline__ void pack4(float4 v, uint32_t* w) {
    __nv_bfloat162 p0(__float2bfloat16(v.x), __float2bfloat16(v.y));
    __nv_bfloat162 p1(__float2bfloat16(v.z), __float2bfloat16(v.w));
    w[0] = *(uint32_t*)&p0;
    w[1] = *(uint32_t*)&p1;
}
// residual of 4 floats vs their bf16 hi parts
__device__ __forceinline__ void pack4res(float4 v, uint32_t* w) {
    __nv_bfloat16 b0 = __float2bfloat16(v.x), b1 = __float2bfloat16(v.y);
    __nv_bfloat16 b2 = __float2bfloat16(v.z), b3 = __float2bfloat16(v.w);
    __nv_bfloat162 p0(__float2bfloat16(v.x - __bfloat162float(b0)),
                      __float2bfloat16(v.y - __bfloat162float(b1)));
    __nv_bfloat162 p1(__float2bfloat16(v.z - __bfloat162float(b2)),
                      __float2bfloat16(v.w - __bfloat162float(b3)));
    w[0] = *(uint32_t*)&p0;
    w[1] = *(uint32_t*)&p1;
}

// convert 8 floats -> one 16B hi store + one 16B lo store (streaming)
__device__ __forceinline__ void split8(const float4* src, int u,
                                       __nv_bfloat16* hi, __nv_bfloat16* lo) {
    float4 v0 = src[2 * (size_t)u];
    float4 v1 = src[2 * (size_t)u + 1];
    uint4 h, l;
    pack4(v0, &h.x);
    pack4(v1, &h.z);
    pack4res(v0, &l.x);
    pack4res(v1, &l.z);
    __stcs((uint4*)(hi + 8 * (size_t)u), h);
    __stcs((uint4*)(lo + 8 * (size_t)u), l);
}
// convert 8 floats -> one 16B bf16 store (streaming)
__device__ __forceinline__ void conv8(const float4* src, int u,
                                      __nv_bfloat16* dst) {
    float4 v0 = src[2 * (size_t)u];
    float4 v1 = src[2 * (size_t)u + 1];
    uint4 h;
    pack4(v0, &h.x);
    pack4(v1, &h.z);
    __stcs((uint4*)(dst + 8 * (size_t)u), h);
}

// ---------------------------------------------------------------------------
// prep: blocks 0-255 = colstats (64 y-rows x 256 cols each),
//       blocks 256-1279 = grid-stride convert at 8 floats/iter
// ---------------------------------------------------------------------------
__global__ void prep_kernel(const float* __restrict__ x,
                            const float* __restrict__ y,
                            const float* __restrict__ wskip,
                            const float* __restrict__ wdec) {
    int b = blockIdx.x;
    if (b < 256) {
        int bx = b & 3, by = b >> 2;          // bx: col group, by: 0..63
        int d  = bx * 256 + threadIdx.x;
        const float* yp = y + (size_t)(by * 64) * DIM + d;
        float s = 0.f, s2 = 0.f;
#pragma unroll 8
        for (int r = 0; r < 64; r++) {
            float v = yp[(size_t)r * DIM];
            s += v; s2 += v * v;
        }
        g_colsum_part[by * DIM + d] = s;
        __shared__ float red[256];
        red[threadIdx.x] = s2;
        __syncthreads();
        for (int st = 128; st > 0; st >>= 1) {
            if (threadIdx.x < st) red[threadIdx.x] += red[threadIdx.x + st];
            __syncthreads();
        }
        if (threadIdx.x == 0) g_s2_part[by * 4 + bx] = red[0];
    } else {
        int i = (b - 256) * blockDim.x + threadIdx.x;
        int stride = 1024 * blockDim.x;
        const int total = XU8 + WU8 + WDU8;
        for (int u = i; u < total; u += stride) {
            if (u < XU8) {
                split8((const float4*)x, u, g_Xh, g_Xl);
            } else if (u < XU8 + WU8) {
                split8((const float4*)wskip, u - XU8, g_Wh, g_Wl);
            } else {
                conv8((const float4*)wdec, u - XU8 - WU8, g_Wdecb);
            }
        }
    }
}

// ---------------------------------------------------------------------------
// Fused (R13/R14 hot loops unchanged):
//   warps 0-7 : 4-stage cp.async HMMA skip-GEMM, spill to ex
//   warps 8-15: sparse decode phases 0-3 (__ldg gather, reg accum), epilogue
//   last CTA computes full fvu in-kernel (incl. colsum reduction)
// tile 128 x 128, grid (8, 32), 512 threads.
// ---------------------------------------------------------------------------
#define LDA 40
#define TILEB (128 * LDA * 2)          // 10240
#define STAGEB (4 * TILEB)             // 40960
#define NSTAGE 4
#define EXLD 132
#define SM_EX    0                     // 67584, overlays stages
#define SM_PAIR  (NSTAGE * STAGEB)     // 163840: uint2[128*16] = 16384
#define SM_RED   (SM_PAIR + 16384)     // 180224
#define SMEM_DYN (SM_RED + 192)        // 180416

__global__ void __launch_bounds__(512, 1)
fused_kernel(const float* __restrict__ y,
             const float* __restrict__ lat_acts,
             const int*   __restrict__ lat_idx,
             const float* __restrict__ b_dec,
             const float* __restrict__ post_enc,
             const float* __restrict__ pes,
             float* __restrict__ out,
             int fvu_idx)
{
    extern __shared__ char smem[];
    const uint32_t sb = smem_to_u32(smem);
    const int tid  = threadIdx.x;
    const int n0 = blockIdx.y * 128;
    const int d0 = blockIdx.x * 128;
    float* ex = (float*)(smem + SM_EX);

    if (tid < 256) {
        // ================= GEMM group (warps 0-7) =========================
        const int wid  = tid >> 5;
        const int lane = tid & 31;
        const int wm = wid & 1;
        const int wn = wid >> 1;

        const __nv_bfloat16* gA[2] = {g_Xh + (size_t)n0 * DIM,
                                      g_Xl + (size_t)n0 * DIM};
        const __nv_bfloat16* gB[2] = {g_Wh + (size_t)d0 * DIM,
                                      g_Wl + (size_t)d0 * DIM};
        const int lrow = tid >> 1;
        const int lseg = (tid & 1) * 2;

        auto issue = [&](int kc) {
            const uint32_t base = sb + (uint32_t)((kc & 3) * STAGEB);
            const size_t gof = (size_t)lrow * DIM + kc * 32 + lseg * 8;
            const uint32_t sof = (uint32_t)(lrow * (LDA * 2) + lseg * 16);
#pragma unroll
            for (int t = 0; t < 2; t++) {
                cp16(base + t * TILEB + sof,            gA[t] + gof);
                cp16(base + t * TILEB + sof + 16,       gA[t] + gof + 8);
                cp16(base + (2 + t) * TILEB + sof,      gB[t] + gof);
                cp16(base + (2 + t) * TILEB + sof + 16, gB[t] + gof + 8);
            }
            CP_COMMIT();
        };

        float acc[4][4][4];
#pragma unroll
        for (int i = 0; i < 4; i++)
#pragma unroll
            for (int j = 0; j < 4; j++)
#pragma unroll
                for (int e = 0; e < 4; e++) acc[i][j][e] = 0.f;

        const uint32_t aoff = (uint32_t)(((((lane >> 3) & 1) * 8 + (lane & 7)) * LDA
                                          + (lane >> 4) * 8) * 2);
        const uint32_t boff = (uint32_t)(((lane & 7) * LDA + ((lane >> 3) & 1) * 8) * 2);
        const uint32_t abase = sb + aoff + (uint32_t)(wm * 64 * LDA * 2);
        const uint32_t bbase = sb + boff + (uint32_t)(wn * 32 * LDA * 2);

        issue(0); issue(1); issue(2);
        for (int kc = 0; kc < 32; kc++) {
            if (kc < 29) { issue(kc + 3); CP_WAIT3(); }
            else         { CP_WAIT0(); }
            NBAR(1, 256);
            const uint32_t stb = (uint32_t)((kc & 3) * STAGEB);
#pragma unroll
            for (int ks = 0; ks < 2; ks++) {
                const uint32_t kb = ks * 32;
                uint32_t bh[4][2], bl[4][2];
#pragma unroll
                for (int nf = 0; nf < 4; nf++) {
                    uint32_t bo = bbase + stb + (uint32_t)(nf * 8 * LDA * 2) + kb;
                    ldsm2(bh[nf], bo + 2 * TILEB);
                    ldsm2(bl[nf], bo + 3 * TILEB);
                }
#pragma unroll
                for (int mf = 0; mf < 4; mf++) {
                    uint32_t ao = abase + stb + (uint32_t)(mf * 16 * LDA * 2) + kb;
                    uint32_t ah[4], al[4];
                    ldsm4(ah, ao);
#pragma unroll
                    for (int nf = 0; nf < 4; nf++) mma16816(acc[mf][nf], ah, bh[nf]);
#pragma unroll
                    for (int nf = 0; nf < 4; nf++) mma16816(acc[mf][nf], ah, bl[nf]);
                    ldsm4(al, ao + TILEB);
#pragma unroll
                    for (int nf = 0; nf < 4; nf++) mma16816(acc[mf][nf], al, bh[nf]);
                }
            }
            NBAR(1, 256);
        }

        // spill accumulators to smem exchange buffer (overlays stage bufs)
        {
            int r0 = wm * 64 + (lane >> 2);
            int c0 = wn * 32 + 2 * (lane & 3);
#pragma unroll
            for (int mf = 0; mf < 4; mf++)
#pragma unroll
                for (int nf = 0; nf < 4; nf++) {
                    int r = r0 + mf * 16, c = c0 + nf * 8;
                    *(float2*)&ex[r * EXLD + c] =
                        make_float2(acc[mf][nf][0], acc[mf][nf][1]);
                    *(float2*)&ex[(r + 8) * EXLD + c] =
                        make_float2(acc[mf][nf][2], acc[mf][nf][3]);
                }
        }
        __syncthreads();   // join with decode group; GEMM warps done
    } else {
        // ================= Decode group (warps 8-15), phases 0-3 ==========
        const int dtid = tid - 256;
        const int tx = dtid & 15;
        const int ty = dtid >> 4;
        uint2* pair_s = (uint2*)(smem + SM_PAIR);  // [128][16]
        const char* wbase = (const char*)g_Wdecb + (size_t)(d0 + tx * 8) * 2;
        float c[8][8];
#pragma unroll
        for (int i = 0; i < 8; i++)
#pragma unroll
            for (int j = 0; j < 8; j++) c[i][j] = 0.f;

        for (int ph = 0; ph < 4; ph++) {
            if (ph > 0) NBAR(2, 256);
#pragma unroll
            for (int q = 0; q < 8; q++) {
                int e = dtid * 8 + q;
                int t = e >> 4, k = e & 15;
                int gi = (n0 + t) * KTOP + ph * 16 + k;
                int id = lat_idx[gi];
                float a = (lat_acts[gi] + post_enc[id]) * pes[id];
                pair_s[t * 16 + k] = make_uint2((uint32_t)id << 11,
                                                __float_as_uint(a));
            }
            NBAR(2, 256);
            for (int k = 0; k < 16; k++) {
#pragma unroll
                for (int i = 0; i < 8; i++) {
                    int t = ty * 8 + i;
                    uint2 p = pair_s[t * 16 + k];
                    float a = __uint_as_float(p.y);
                    uint4 u = __ldg((const uint4*)(wbase + p.x));
                    c[i][0] += a * bf_lo(u.x); c[i][1] += a * bf_hi(u.x);
                    c[i][2] += a * bf_lo(u.y); c[i][3] += a * bf_hi(u.y);
                    c[i][4] += a * bf_lo(u.z); c[i][5] += a * bf_hi(u.z);
                    c[i][6] += a * bf_lo(u.w); c[i][7] += a * bf_hi(u.w);
                }
            }
        }
        __syncthreads();   // join: GEMM skip results now in ex

        // ---- epilogue: skip + decode + b_dec -> out, err partial --------
        float err = 0.f;
#pragma unroll
        for (int i = 0; i < 8; i++) {
            int t = ty * 8 + i;
            int n = n0 + t;
#pragma unroll
            for (int j = 0; j < 8; j += 4) {
                int d = d0 + tx * 8 + j;
                float4 bd = *(const float4*)&b_dec[d];
                float4 yv = *(const float4*)&y[(size_t)n * DIM + d];
                float4 sv = *(const float4*)&ex[t * EXLD + tx * 8 + j];
                float4 o;
                o.x = c[i][j + 0] + sv.x + bd.x;
                o.y = c[i][j + 1] + sv.y + bd.y;
                o.z = c[i][j + 2] + sv.z + bd.z;
                o.w = c[i][j + 3] + sv.w + bd.w;
                *(float4*)&out[(size_t)n * DIM + d] = o;
                float e0 = yv.x - o.x, e1 = yv.y - o.y;
                float e2 = yv.z - o.z, e3 = yv.w - o.w;
                err += e0 * e0 + e1 * e1 + e2 * e2 + e3 * e3;
            }
        }

        float* red = (float*)(smem + SM_RED);
        int* flag = (int*)(red + 8);
#pragma unroll
        for (int off = 16; off > 0; off >>= 1)
            err += __shfl_down_sync(0xFFFFFFFFu, err, off);
        if ((dtid & 31) == 0) red[dtid >> 5] = err;
        NBAR(2, 256);
        if (dtid == 0) {
            float s = 0.f;
#pragma unroll
            for (int q = 0; q < 8; q++) s += red[q];
            g_err_part[blockIdx.y * gridDim.x + blockIdx.x] = s;
            __threadfence();
            int r = atomicAdd(&g_done, 1);
            *flag = (r == (int)(gridDim.x * gridDim.y) - 1) ? 1 : 0;
        }
        NBAR(2, 256);

        // ---- last CTA: full fvu (incl. colsum reduction) ----------------
        if (*flag) {
            if (dtid == 0) __threadfence();   // acquire side
            NBAR(2, 256);
            float csq = 0.f;
#pragma unroll
            for (int q = 0; q < 4; q++) {
                int col = dtid + q * 256;
                float cs = 0.f;
#pragma unroll 8
                for (int r = 0; r < 64; r++)
                    cs += g_colsum_part[r * DIM + col];
                csq += cs * cs;
            }
            float s2 = (dtid < 256) ? g_s2_part[dtid] : 0.f;
            float er = g_err_part[dtid];
#pragma unroll
            for (int off = 16; off > 0; off >>= 1) {
                csq += __shfl_down_sync(0xFFFFFFFFu, csq, off);
                s2  += __shfl_down_sync(0xFFFFFFFFu, s2,  off);
                er  += __shfl_down_sync(0xFFFFFFFFu, er,  off);
            }
            float* r3 = red + 12;
            if ((dtid & 31) == 0) {
                r3[dtid >> 5]      = csq;
                r3[8 + (dtid >> 5)]  = s2;
                r3[16 + (dtid >> 5)] = er;
            }
            NBAR(2, 256);
            if (dtid == 0) {
                float a = 0.f, b = 0.f, e = 0.f;
#pragma unroll
                for (int q = 0; q < 8; q++) {
                    a += r3[q]; b += r3[8 + q]; e += r3[16 + q];
                }
                float tv = b - a / (float)NTOK;
                out[fvu_idx] = e / tv;
                g_done = 0;      // reset for next graph replay
            }
        }
    }
}

extern "C" void kernel_launch(void* const* d_in, const int* in_sizes, int n_in,
                              void* d_out, int out_size)
{
    const float* x        = (const float*)d_in[0];
    const float* y        = (const float*)d_in[1];
    const float* lat_acts = (const float*)d_in[2];
    const int*   lat_idx  = (const int*)  d_in[3];
    const float* W_dec    = (const float*)d_in[4];
    const float* b_dec    = (const float*)d_in[5];
    const float* post_enc = (const float*)d_in[6];
    const float* pes      = (const float*)d_in[7];
    const float* W_skip   = (const float*)d_in[8];
    float* out = (float*)d_out;

    cudaFuncSetAttribute(fused_kernel,
                         cudaFuncAttributeMaxDynamicSharedMemorySize, SMEM_DYN);

    prep_kernel<<<1280, 256>>>(x, y, W_skip, W_dec);
    fused_kernel<<<dim3(8, 32), 512, SMEM_DYN>>>(
        y, lat_acts, lat_idx, b_dec, post_enc, pes, out, out_size - 1);
}

// round 16
// speedup vs baseline: 1.0484x; 1.0484x over previous
#include <cuda_runtime.h>
#include <cuda_bf16.h>
#include <cstdint>

#define NTOK 4096
#define KTOP 64
#define DIM  1024
#define NLAT 16384

__device__ __nv_bfloat16 g_Xh[NTOK * DIM];
__device__ __nv_bfloat16 g_Xl[NTOK * DIM];
__device__ __nv_bfloat16 g_Wh[DIM * DIM];
__device__ __nv_bfloat16 g_Wl[DIM * DIM];
__device__ __nv_bfloat16 g_Wdecb[NLAT * DIM];
__device__ float g_colsum_part[64 * DIM];
__device__ float g_colsum[DIM];
__device__ float g_s2_part[64 * 4];
__device__ float g_err_part[256];
__device__ int   g_done;          // zero-initialized; reset by finalizer

__device__ __forceinline__ void mma16816(float* d, const uint32_t* a,
                                         const uint32_t* b) {
    asm volatile(
        "mma.sync.aligned.m16n8k16.row.col.f32.bf16.bf16.f32 "
        "{%0,%1,%2,%3}, {%4,%5,%6,%7}, {%8,%9}, {%0,%1,%2,%3};"
        : "+f"(d[0]), "+f"(d[1]), "+f"(d[2]), "+f"(d[3])
        : "r"(a[0]), "r"(a[1]), "r"(a[2]), "r"(a[3]), "r"(b[0]), "r"(b[1]));
}
__device__ __forceinline__ void ldsm4(uint32_t* r, uint32_t addr) {
    asm volatile("ldmatrix.sync.aligned.m8n8.x4.shared.b16 {%0,%1,%2,%3}, [%4];"
                 : "=r"(r[0]), "=r"(r[1]), "=r"(r[2]), "=r"(r[3]) : "r"(addr));
}
__device__ __forceinline__ void ldsm2(uint32_t* r, uint32_t addr) {
    asm volatile("ldmatrix.sync.aligned.m8n8.x2.shared.b16 {%0,%1}, [%2];"
                 : "=r"(r[0]), "=r"(r[1]) : "r"(addr));
}
__device__ __forceinline__ uint32_t smem_to_u32(const void* p) {
    uint32_t a;
    asm("{ .reg .u64 t; cvta.to.shared.u64 t, %1; cvt.u32.u64 %0, t; }"
        : "=r"(a) : "l"(p));
    return a;
}
__device__ __forceinline__ void cp16(uint32_t dst, const void* src) {
    asm volatile("cp.async.cg.shared.global [%0], [%1], 16;"
                 :: "r"(dst), "l"(src) : "memory");
}
#define CP_COMMIT() asm volatile("cp.async.commit_group;" ::: "memory")
#define CP_WAIT3()  asm volatile("cp.async.wait_group 3;" ::: "memory")
#define CP_WAIT0()  asm volatile("cp.async.wait_group 0;" ::: "memory")
#define NBAR(id, cnt) \
    asm volatile("bar.sync %0, %1;" :: "r"(id), "r"(cnt) : "memory")

__device__ __forceinline__ float bf_hi(uint32_t r) {
    return __uint_as_float(r & 0xFFFF0000u);
}
__device__ __forceinline__ float bf_lo(uint32_t r) {
    return __uint_as_float(r << 16);
}

#define XU8  (NTOK * DIM / 8)
#define WU8  (DIM * DIM / 8)
#define WDU8 (NLAT * DIM / 8)

// pack 4 floats -> 2 bf16x2 words
__device__ __forceinline__ void pack4(float4 v, uint32_t* w) {
    __nv_bfloat162 p0(__float2bfloat16(v.x), __float2bfloat16(v.y));
    __nv_bfloat162 p1(__float2bfloat16(v.z), __float2bfloat16(v.w));
    w[0] = *(uint32_t*)&p0;
    w[1] = *(uint32_t*)&p1;
}
// residual of 4 floats vs their bf16 hi parts
__device__ __forceinline__ void pack4res(float4 v, uint32_t* w) {
    __nv_bfloat16 b0 = __float2bfloat16(v.x), b1 = __float2bfloat16(v.y);
    __nv_bfloat16 b2 = __float2bfloat16(v.z), b3 = __float2bfloat16(v.w);
    __nv_bfloat162 p0(__float2bfloat16(v.x - __bfloat162float(b0)),
                      __float2bfloat16(v.y - __bfloat162float(b1)));
    __nv_bfloat162 p1(__float2bfloat16(v.z - __bfloat162float(b2)),
                      __float2bfloat16(v.w - __bfloat162float(b3)));
    w[0] = *(uint32_t*)&p0;
    w[1] = *(uint32_t*)&p1;
}

// convert 8 floats -> one 16B hi store + one 16B lo store
__device__ __forceinline__ void split8(const float4* src, int u,
                                       __nv_bfloat16* hi, __nv_bfloat16* lo) {
    float4 v0 = src[2 * (size_t)u];
    float4 v1 = src[2 * (size_t)u + 1];
    uint4 h, l;
    pack4(v0, &h.x);
    pack4(v1, &h.z);
    pack4res(v0, &l.x);
    pack4res(v1, &l.z);
    *(uint4*)(hi + 8 * (size_t)u) = h;
    *(uint4*)(lo + 8 * (size_t)u) = l;
}
// convert 8 floats -> one 16B bf16 store
__device__ __forceinline__ void conv8(const float4* src, int u,
                                      __nv_bfloat16* dst) {
    float4 v0 = src[2 * (size_t)u];
    float4 v1 = src[2 * (size_t)u + 1];
    uint4 h;
    pack4(v0, &h.x);
    pack4(v1, &h.z);
    *(uint4*)(dst + 8 * (size_t)u) = h;
}

// ---------------------------------------------------------------------------
// prep: blocks 0-255 = colstats (64 y-rows x 256 cols each),
//       blocks 256-1279 = grid-stride convert at 8 floats/iter
// ---------------------------------------------------------------------------
__global__ void prep_kernel(const float* __restrict__ x,
                            const float* __restrict__ y,
                            const float* __restrict__ wskip,
                            const float* __restrict__ wdec) {
    int b = blockIdx.x;
    if (b < 256) {
        int bx = b & 3, by = b >> 2;          // bx: col group, by: 0..63
        int d  = bx * 256 + threadIdx.x;
        const float* yp = y + (size_t)(by * 64) * DIM + d;
        float s = 0.f, s2 = 0.f;
#pragma unroll 8
        for (int r = 0; r < 64; r++) {
            float v = yp[(size_t)r * DIM];
            s += v; s2 += v * v;
        }
        g_colsum_part[by * DIM + d] = s;
        __shared__ float red[256];
        red[threadIdx.x] = s2;
        __syncthreads();
        for (int st = 128; st > 0; st >>= 1) {
            if (threadIdx.x < st) red[threadIdx.x] += red[threadIdx.x + st];
            __syncthreads();
        }
        if (threadIdx.x == 0) g_s2_part[by * 4 + bx] = red[0];
    } else {
        int i = (b - 256) * blockDim.x + threadIdx.x;
        int stride = 1024 * blockDim.x;
        const int total = XU8 + WU8 + WDU8;
        for (int u = i; u < total; u += stride) {
            if (u < XU8) {
                split8((const float4*)x, u, g_Xh, g_Xl);
            } else if (u < XU8 + WU8) {
                split8((const float4*)wskip, u - XU8, g_Wh, g_Wl);
            } else {
                conv8((const float4*)wdec, u - XU8 - WU8, g_Wdecb);
            }
        }
    }
}

// ---------------------------------------------------------------------------
// reduce_colsum: collapse 64 row-partials -> g_colsum[1024]. grid 32 x 256.
// ---------------------------------------------------------------------------
__global__ void reduce_colsum_kernel() {
    int t = threadIdx.x;
    int lane = t & 31, seg = t >> 5;          // 8 segs of 8 rows
    int col = blockIdx.x * 32 + lane;
    float s = 0.f;
#pragma unroll
    for (int r = 0; r < 8; r++)
        s += g_colsum_part[(seg * 8 + r) * DIM + col];
    __shared__ float sm[8][32];
    sm[seg][lane] = s;
    __syncthreads();
    if (seg == 0) {
        float v = sm[0][lane];
#pragma unroll
        for (int q = 1; q < 8; q++) v += sm[q][lane];
        g_colsum[col] = v;
    }
}

// ---------------------------------------------------------------------------
// Fused (R14 hot loops; decode merged to 2 phases of 32 k):
//   warps 0-7 : 4-stage cp.async HMMA skip-GEMM, spill to ex
//   warps 8-15: sparse decode (__ldg gather, reg accum), epilogue
//   last CTA computes fvu from precomputed g_colsum (coalesced path)
// tile 128 x 128, grid (8, 32), 512 threads.
// ---------------------------------------------------------------------------
#define LDA 40
#define TILEB (128 * LDA * 2)          // 10240
#define STAGEB (4 * TILEB)             // 40960
#define NSTAGE 4
#define EXLD 132
#define SM_EX    0                     // 67584, overlays stages
#define SM_PAIR  (NSTAGE * STAGEB)     // 163840: uint2[128*32] = 32768
#define SM_RED   (SM_PAIR + 32768)     // 196608
#define SMEM_DYN (SM_RED + 192)        // 196800

__global__ void __launch_bounds__(512, 1)
fused_kernel(const float* __restrict__ y,
             const float* __restrict__ lat_acts,
             const int*   __restrict__ lat_idx,
             const float* __restrict__ b_dec,
             const float* __restrict__ post_enc,
             const float* __restrict__ pes,
             float* __restrict__ out,
             int fvu_idx)
{
    extern __shared__ char smem[];
    const uint32_t sb = smem_to_u32(smem);
    const int tid  = threadIdx.x;
    const int n0 = blockIdx.y * 128;
    const int d0 = blockIdx.x * 128;
    float* ex = (float*)(smem + SM_EX);

    if (tid < 256) {
        // ================= GEMM group (warps 0-7) =========================
        const int wid  = tid >> 5;
        const int lane = tid & 31;
        const int wm = wid & 1;
        const int wn = wid >> 1;

        const __nv_bfloat16* gA[2] = {g_Xh + (size_t)n0 * DIM,
                                      g_Xl + (size_t)n0 * DIM};
        const __nv_bfloat16* gB[2] = {g_Wh + (size_t)d0 * DIM,
                                      g_Wl + (size_t)d0 * DIM};
        const int lrow = tid >> 1;
        const int lseg = (tid & 1) * 2;

        auto issue = [&](int kc) {
            const uint32_t base = sb + (uint32_t)((kc & 3) * STAGEB);
            const size_t gof = (size_t)lrow * DIM + kc * 32 + lseg * 8;
            const uint32_t sof = (uint32_t)(lrow * (LDA * 2) + lseg * 16);
#pragma unroll
            for (int t = 0; t < 2; t++) {
                cp16(base + t * TILEB + sof,            gA[t] + gof);
                cp16(base + t * TILEB + sof + 16,       gA[t] + gof + 8);
                cp16(base + (2 + t) * TILEB + sof,      gB[t] + gof);
                cp16(base + (2 + t) * TILEB + sof + 16, gB[t] + gof + 8);
            }
            CP_COMMIT();
        };

        float acc[4][4][4];
#pragma unroll
        for (int i = 0; i < 4; i++)
#pragma unroll
            for (int j = 0; j < 4; j++)
#pragma unroll
                for (int e = 0; e < 4; e++) acc[i][j][e] = 0.f;

        const uint32_t aoff = (uint32_t)(((((lane >> 3) & 1) * 8 + (lane & 7)) * LDA
                                          + (lane >> 4) * 8) * 2);
        const uint32_t boff = (uint32_t)(((lane & 7) * LDA + ((lane >> 3) & 1) * 8) * 2);
        const uint32_t abase = sb + aoff + (uint32_t)(wm * 64 * LDA * 2);
        const uint32_t bbase = sb + boff + (uint32_t)(wn * 32 * LDA * 2);

        issue(0); issue(1); issue(2);
        for (int kc = 0; kc < 32; kc++) {
            if (kc < 29) { issue(kc + 3); CP_WAIT3(); }
            else         { CP_WAIT0(); }
            NBAR(1, 256);
            const uint32_t stb = (uint32_t)((kc & 3) * STAGEB);
#pragma unroll
            for (int ks = 0; ks < 2; ks++) {
                const uint32_t kb = ks * 32;
                uint32_t bh[4][2], bl[4][2];
#pragma unroll
                for (int nf = 0; nf < 4; nf++) {
                    uint32_t bo = bbase + stb + (uint32_t)(nf * 8 * LDA * 2) + kb;
                    ldsm2(bh[nf], bo + 2 * TILEB);
                    ldsm2(bl[nf], bo + 3 * TILEB);
                }
#pragma unroll
                for (int mf = 0; mf < 4; mf++) {
                    uint32_t ao = abase + stb + (uint32_t)(mf * 16 * LDA * 2) + kb;
                    uint32_t ah[4], al[4];
                    ldsm4(ah, ao);
#pragma unroll
                    for (int nf = 0; nf < 4; nf++) mma16816(acc[mf][nf], ah, bh[nf]);
#pragma unroll
                    for (int nf = 0; nf < 4; nf++) mma16816(acc[mf][nf], ah, bl[nf]);
                    ldsm4(al, ao + TILEB);
#pragma unroll
                    for (int nf = 0; nf < 4; nf++) mma16816(acc[mf][nf], al, bh[nf]);
                }
            }
            NBAR(1, 256);
        }

        // spill accumulators to smem exchange buffer (overlays stage bufs)
        {
            int r0 = wm * 64 + (lane >> 2);
            int c0 = wn * 32 + 2 * (lane & 3);
#pragma unroll
            for (int mf = 0; mf < 4; mf++)
#pragma unroll
                for (int nf = 0; nf < 4; nf++) {
                    int r = r0 + mf * 16, c = c0 + nf * 8;
                    *(float2*)&ex[r * EXLD + c] =
                        make_float2(acc[mf][nf][0], acc[mf][nf][1]);
                    *(float2*)&ex[(r + 8) * EXLD + c] =
                        make_float2(acc[mf][nf][2], acc[mf][nf][3]);
                }
        }
        __syncthreads();   // join with decode group; GEMM warps done
    } else {
        // ============ Decode group (warps 8-15), 2 phases of 32 k =========
        const int dtid = tid - 256;
        const int tx = dtid & 15;
        const int ty = dtid >> 4;
        uint2* pair_s = (uint2*)(smem + SM_PAIR);  // [128][32]
        const char* wbase = (const char*)g_Wdecb + (size_t)(d0 + tx * 8) * 2;
        float c[8][8];
#pragma unroll
        for (int i = 0; i < 8; i++)
#pragma unroll
            for (int j = 0; j < 8; j++) c[i][j] = 0.f;

        for (int ph = 0; ph < 2; ph++) {
            if (ph > 0) NBAR(2, 256);
#pragma unroll
            for (int q = 0; q < 16; q++) {
                int e = dtid * 16 + q;
                int t = e >> 5, k = e & 31;
                int gi = (n0 + t) * KTOP + ph * 32 + k;
                int id = lat_idx[gi];
                float a = (lat_acts[gi] + post_enc[id]) * pes[id];
                pair_s[t * 32 + k] = make_uint2((uint32_t)id << 11,
                                                __float_as_uint(a));
            }
            NBAR(2, 256);
            for (int k = 0; k < 32; k++) {
#pragma unroll
                for (int i = 0; i < 8; i++) {
                    int t = ty * 8 + i;
                    uint2 p = pair_s[t * 32 + k];
                    float a = __uint_as_float(p.y);
                    uint4 u = __ldg((const uint4*)(wbase + p.x));
                    c[i][0] += a * bf_lo(u.x); c[i][1] += a * bf_hi(u.x);
                    c[i][2] += a * bf_lo(u.y); c[i][3] += a * bf_hi(u.y);
                    c[i][4] += a * bf_lo(u.z); c[i][5] += a * bf_hi(u.z);
                    c[i][6] += a * bf_lo(u.w); c[i][7] += a * bf_hi(u.w);
                }
            }
        }
        __syncthreads();   // join: GEMM skip results now in ex

        // ---- epilogue: skip + decode + b_dec -> out, err partial --------
        float err = 0.f;
#pragma unroll
        for (int i = 0; i < 8; i++) {
            int t = ty * 8 + i;
            int n = n0 + t;
#pragma unroll
            for (int j = 0; j < 8; j += 4) {
                int d = d0 + tx * 8 + j;
                float4 bd = *(const float4*)&b_dec[d];
                float4 yv = *(const float4*)&y[(size_t)n * DIM + d];
                float4 sv = *(const float4*)&ex[t * EXLD + tx * 8 + j];
                float4 o;
                o.x = c[i][j + 0] + sv.x + bd.x;
                o.y = c[i][j + 1] + sv.y + bd.y;
                o.z = c[i][j + 2] + sv.z + bd.z;
                o.w = c[i][j + 3] + sv.w + bd.w;
                *(float4*)&out[(size_t)n * DIM + d] = o;
                float e0 = yv.x - o.x, e1 = yv.y - o.y;
                float e2 = yv.z - o.z, e3 = yv.w - o.w;
                err += e0 * e0 + e1 * e1 + e2 * e2 + e3 * e3;
            }
        }

        float* red = (float*)(smem + SM_RED);
        int* flag = (int*)(red + 8);
#pragma unroll
        for (int off = 16; off > 0; off >>= 1)
            err += __shfl_down_sync(0xFFFFFFFFu, err, off);
        if ((dtid & 31) == 0) red[dtid >> 5] = err;
        NBAR(2, 256);
        if (dtid == 0) {
            float s = 0.f;
#pragma unroll
            for (int q = 0; q < 8; q++) s += red[q];
            g_err_part[blockIdx.y * gridDim.x + blockIdx.x] = s;
            __threadfence();
            int r = atomicAdd(&g_done, 1);
            *flag = (r == (int)(gridDim.x * gridDim.y) - 1) ? 1 : 0;
        }
        NBAR(2, 256);

        // ---- last CTA: fvu from g_colsum (coalesced) --------------------
        if (*flag) {
            if (dtid == 0) __threadfence();   // acquire side
            NBAR(2, 256);
            float csq = 0.f;
#pragma unroll
            for (int q = 0; q < 4; q++) {
                float cs = g_colsum[dtid + q * 256];
                csq += cs * cs;
            }
            float s2 = (dtid < 256) ? g_s2_part[dtid] : 0.f;
            float er = g_err_part[dtid];
#pragma unroll
            for (int off = 16; off > 0; off >>= 1) {
                csq += __shfl_down_sync(0xFFFFFFFFu, csq, off);
                s2  += __shfl_down_sync(0xFFFFFFFFu, s2,  off);
                er  += __shfl_down_sync(0xFFFFFFFFu, er,  off);
            }
            float* r3 = red + 12;
            if ((dtid & 31) == 0) {
                r3[dtid >> 5]      = csq;
                r3[8 + (dtid >> 5)]  = s2;
                r3[16 + (dtid >> 5)] = er;
            }
            NBAR(2, 256);
            if (dtid == 0) {
                float a = 0.f, b = 0.f, e = 0.f;
#pragma unroll
                for (int q = 0; q < 8; q++) {
                    a += r3[q]; b += r3[8 + q]; e += r3[16 + q];
                }
                float tv = b - a / (float)NTOK;
                out[fvu_idx] = e / tv;
                g_done = 0;      // reset for next graph replay
            }
        }
    }
}

extern "C" void kernel_launch(void* const* d_in, const int* in_sizes, int n_in,
                              void* d_out, int out_size)
{
    const float* x        = (const float*)d_in[0];
    const float* y        = (const float*)d_in[1];
    const float* lat_acts = (const float*)d_in[2];
    const int*   lat_idx  = (const int*)  d_in[3];
    const float* W_dec    = (const float*)d_in[4];
    const float* b_dec    = (const float*)d_in[5];
    const float* post_enc = (const float*)d_in[6];
    const float* pes      = (const float*)d_in[7];
    const float* W_skip   = (const float*)d_in[8];
    float* out = (float*)d_out;

    cudaFuncSetAttribute(fused_kernel,
                         cudaFuncAttributeMaxDynamicSharedMemorySize, SMEM_DYN);

    prep_kernel<<<1280, 256>>>(x, y, W_skip, W_dec);
    reduce_colsum_kernel<<<32, 256>>>();
    fused_kernel<<<dim3(8, 32), 512, SMEM_DYN>>>(
        y, lat_acts, lat_idx, b_dec, post_enc, pes, out, out_size - 1);
}

// round 17
// speedup vs baseline: 1.0952x; 1.0446x over previous
#include <cuda_runtime.h>
#include <cuda_bf16.h>
#include <cstdint>

#define NTOK 4096
#define KTOP 64
#define DIM  1024
#define NLAT 16384

__device__ __nv_bfloat16 g_Xh[NTOK * DIM];
__device__ __nv_bfloat16 g_Xl[NTOK * DIM];
__device__ __nv_bfloat16 g_Wh[DIM * DIM];
__device__ __nv_bfloat16 g_Wl[DIM * DIM];
__device__ __nv_bfloat16 g_Wdecb[NLAT * DIM];
__device__ float g_colsum_part[64 * DIM];
__device__ float g_colsum[DIM];
__device__ float g_s2_part[64 * 4];
__device__ float g_err_part[256];
__device__ int   g_done;          // zero-initialized; reset by finalizer

__device__ __forceinline__ void mma16816(float* d, const uint32_t* a,
                                         const uint32_t* b) {
    asm volatile(
        "mma.sync.aligned.m16n8k16.row.col.f32.bf16.bf16.f32 "
        "{%0,%1,%2,%3}, {%4,%5,%6,%7}, {%8,%9}, {%0,%1,%2,%3};"
        : "+f"(d[0]), "+f"(d[1]), "+f"(d[2]), "+f"(d[3])
        : "r"(a[0]), "r"(a[1]), "r"(a[2]), "r"(a[3]), "r"(b[0]), "r"(b[1]));
}
__device__ __forceinline__ void ldsm4(uint32_t* r, uint32_t addr) {
    asm volatile("ldmatrix.sync.aligned.m8n8.x4.shared.b16 {%0,%1,%2,%3}, [%4];"
                 : "=r"(r[0]), "=r"(r[1]), "=r"(r[2]), "=r"(r[3]) : "r"(addr));
}
__device__ __forceinline__ void ldsm2(uint32_t* r, uint32_t addr) {
    asm volatile("ldmatrix.sync.aligned.m8n8.x2.shared.b16 {%0,%1}, [%2];"
                 : "=r"(r[0]), "=r"(r[1]) : "r"(addr));
}
__device__ __forceinline__ uint32_t smem_to_u32(const void* p) {
    uint32_t a;
    asm("{ .reg .u64 t; cvta.to.shared.u64 t, %1; cvt.u32.u64 %0, t; }"
        : "=r"(a) : "l"(p));
    return a;
}
__device__ __forceinline__ void cp16(uint32_t dst, const void* src) {
    asm volatile("cp.async.cg.shared.global [%0], [%1], 16;"
                 :: "r"(dst), "l"(src) : "memory");
}
#define CP_COMMIT() asm volatile("cp.async.commit_group;" ::: "memory")
#define CP_WAIT3()  asm volatile("cp.async.wait_group 3;" ::: "memory")
#define CP_WAIT0()  asm volatile("cp.async.wait_group 0;" ::: "memory")
#define NBAR(id, cnt) \
    asm volatile("bar.sync %0, %1;" :: "r"(id), "r"(cnt) : "memory")

__device__ __forceinline__ float bf_hi(uint32_t r) {
    return __uint_as_float(r & 0xFFFF0000u);
}
__device__ __forceinline__ float bf_lo(uint32_t r) {
    return __uint_as_float(r << 16);
}

#define XU8  (NTOK * DIM / 8)
#define WU8  (DIM * DIM / 8)
#define WDU8 (NLAT * DIM / 8)

// pack 4 floats -> 2 bf16x2 words
__device__ __forceinline__ void pack4(float4 v, uint32_t* w) {
    __nv_bfloat162 p0(__float2bfloat16(v.x), __float2bfloat16(v.y));
    __nv_bfloat162 p1(__float2bfloat16(v.z), __float2bfloat16(v.w));
    w[0] = *(uint32_t*)&p0;
    w[1] = *(uint32_t*)&p1;
}
// residual of 4 floats vs their bf16 hi parts
__device__ __forceinline__ void pack4res(float4 v, uint32_t* w) {
    __nv_bfloat16 b0 = __float2bfloat16(v.x), b1 = __float2bfloat16(v.y);
    __nv_bfloat16 b2 = __float2bfloat16(v.z), b3 = __float2bfloat16(v.w);
    __nv_bfloat162 p0(__float2bfloat16(v.x - __bfloat162float(b0)),
                      __float2bfloat16(v.y - __bfloat162float(b1)));
    __nv_bfloat162 p1(__float2bfloat16(v.z - __bfloat162float(b2)),
                      __float2bfloat16(v.w - __bfloat162float(b3)));
    w[0] = *(uint32_t*)&p0;
    w[1] = *(uint32_t*)&p1;
}

// convert 8 floats -> one 16B hi store + one 16B lo store
__device__ __forceinline__ void split8(const float4* src, int u,
                                       __nv_bfloat16* hi, __nv_bfloat16* lo) {
    float4 v0 = src[2 * (size_t)u];
    float4 v1 = src[2 * (size_t)u + 1];
    uint4 h, l;
    pack4(v0, &h.x);
    pack4(v1, &h.z);
    pack4res(v0, &l.x);
    pack4res(v1, &l.z);
    *(uint4*)(hi + 8 * (size_t)u) = h;
    *(uint4*)(lo + 8 * (size_t)u) = l;
}
// convert 8 floats -> one 16B bf16 store
__device__ __forceinline__ void conv8(const float4* src, int u,
                                      __nv_bfloat16* dst) {
    float4 v0 = src[2 * (size_t)u];
    float4 v1 = src[2 * (size_t)u + 1];
    uint4 h;
    pack4(v0, &h.x);
    pack4(v1, &h.z);
    *(uint4*)(dst + 8 * (size_t)u) = h;
}

// ---------------------------------------------------------------------------
// prep: blocks 0-255 = colstats (64 y-rows x 256 cols each),
//       blocks 256-1279 = grid-stride convert at 8 floats/iter
// ---------------------------------------------------------------------------
__global__ void prep_kernel(const float* __restrict__ x,
                            const float* __restrict__ y,
                            const float* __restrict__ wskip,
                            const float* __restrict__ wdec) {
    int b = blockIdx.x;
    if (b < 256) {
        int bx = b & 3, by = b >> 2;          // bx: col group, by: 0..63
        int d  = bx * 256 + threadIdx.x;
        const float* yp = y + (size_t)(by * 64) * DIM + d;
        float s = 0.f, s2 = 0.f;
#pragma unroll 8
        for (int r = 0; r < 64; r++) {
            float v = yp[(size_t)r * DIM];
            s += v; s2 += v * v;
        }
        g_colsum_part[by * DIM + d] = s;
        __shared__ float red[256];
        red[threadIdx.x] = s2;
        __syncthreads();
        for (int st = 128; st > 0; st >>= 1) {
            if (threadIdx.x < st) red[threadIdx.x] += red[threadIdx.x + st];
            __syncthreads();
        }
        if (threadIdx.x == 0) g_s2_part[by * 4 + bx] = red[0];
    } else {
        int i = (b - 256) * blockDim.x + threadIdx.x;
        int stride = 1024 * blockDim.x;
        const int total = XU8 + WU8 + WDU8;
        for (int u = i; u < total; u += stride) {
            if (u < XU8) {
                split8((const float4*)x, u, g_Xh, g_Xl);
            } else if (u < XU8 + WU8) {
                split8((const float4*)wskip, u - XU8, g_Wh, g_Wl);
            } else {
                conv8((const float4*)wdec, u - XU8 - WU8, g_Wdecb);
            }
        }
    }
}

// ---------------------------------------------------------------------------
// reduce_colsum: collapse 64 row-partials -> g_colsum[1024]. grid 32 x 256.
// ---------------------------------------------------------------------------
__global__ void reduce_colsum_kernel() {
    int t = threadIdx.x;
    int lane = t & 31, seg = t >> 5;          // 8 segs of 8 rows
    int col = blockIdx.x * 32 + lane;
    float s = 0.f;
#pragma unroll
    for (int r = 0; r < 8; r++)
        s += g_colsum_part[(seg * 8 + r) * DIM + col];
    __shared__ float sm[8][32];
    sm[seg][lane] = s;
    __syncthreads();
    if (seg == 0) {
        float v = sm[0][lane];
#pragma unroll
        for (int q = 1; q < 8; q++) v += sm[q][lane];
        g_colsum[col] = v;
    }
}

// ---------------------------------------------------------------------------
// Fused (champion R14 structure):
//   warps 0-7 : 4-stage cp.async HMMA skip-GEMM, spill to ex
//   warps 8-15: sparse decode phases 0-3 (__ldg gather, reg accum), epilogue
//   last CTA computes fvu from precomputed g_colsum (coalesced path)
// tile 128 x 128, grid (8, 32), 512 threads.
// ---------------------------------------------------------------------------
#define LDA 40
#define TILEB (128 * LDA * 2)          // 10240
#define STAGEB (4 * TILEB)             // 40960
#define NSTAGE 4
#define EXLD 132
#define SM_EX    0                     // 67584, overlays stages
#define SM_PAIR  (NSTAGE * STAGEB)     // 163840: uint2[128*16] = 16384
#define SM_RED   (SM_PAIR + 16384)     // 180224
#define SMEM_DYN (SM_RED + 192)        // 180416

__global__ void __launch_bounds__(512, 1)
fused_kernel(const float* __restrict__ y,
             const float* __restrict__ lat_acts,
             const int*   __restrict__ lat_idx,
             const float* __restrict__ b_dec,
             const float* __restrict__ post_enc,
             const float* __restrict__ pes,
             float* __restrict__ out,
             int fvu_idx)
{
    extern __shared__ char smem[];
    const uint32_t sb = smem_to_u32(smem);
    const int tid  = threadIdx.x;
    const int n0 = blockIdx.y * 128;
    const int d0 = blockIdx.x * 128;
    float* ex = (float*)(smem + SM_EX);

    if (tid < 256) {
        // ================= GEMM group (warps 0-7) =========================
        const int wid  = tid >> 5;
        const int lane = tid & 31;
        const int wm = wid & 1;
        const int wn = wid >> 1;

        const __nv_bfloat16* gA[2] = {g_Xh + (size_t)n0 * DIM,
                                      g_Xl + (size_t)n0 * DIM};
        const __nv_bfloat16* gB[2] = {g_Wh + (size_t)d0 * DIM,
                                      g_Wl + (size_t)d0 * DIM};
        const int lrow = tid >> 1;
        const int lseg = (tid & 1) * 2;

        auto issue = [&](int kc) {
            const uint32_t base = sb + (uint32_t)((kc & 3) * STAGEB);
            const size_t gof = (size_t)lrow * DIM + kc * 32 + lseg * 8;
            const uint32_t sof = (uint32_t)(lrow * (LDA * 2) + lseg * 16);
#pragma unroll
            for (int t = 0; t < 2; t++) {
                cp16(base + t * TILEB + sof,            gA[t] + gof);
                cp16(base + t * TILEB + sof + 16,       gA[t] + gof + 8);
                cp16(base + (2 + t) * TILEB + sof,      gB[t] + gof);
                cp16(base + (2 + t) * TILEB + sof + 16, gB[t] + gof + 8);
            }
            CP_COMMIT();
        };

        float acc[4][4][4];
#pragma unroll
        for (int i = 0; i < 4; i++)
#pragma unroll
            for (int j = 0; j < 4; j++)
#pragma unroll
                for (int e = 0; e < 4; e++) acc[i][j][e] = 0.f;

        const uint32_t aoff = (uint32_t)(((((lane >> 3) & 1) * 8 + (lane & 7)) * LDA
                                          + (lane >> 4) * 8) * 2);
        const uint32_t boff = (uint32_t)(((lane & 7) * LDA + ((lane >> 3) & 1) * 8) * 2);
        const uint32_t abase = sb + aoff + (uint32_t)(wm * 64 * LDA * 2);
        const uint32_t bbase = sb + boff + (uint32_t)(wn * 32 * LDA * 2);

        issue(0); issue(1); issue(2);
        for (int kc = 0; kc < 32; kc++) {
            if (kc < 29) { issue(kc + 3); CP_WAIT3(); }
            else         { CP_WAIT0(); }
            NBAR(1, 256);
            const uint32_t stb = (uint32_t)((kc & 3) * STAGEB);
#pragma unroll
            for (int ks = 0; ks < 2; ks++) {
                const uint32_t kb = ks * 32;
                uint32_t bh[4][2], bl[4][2];
#pragma unroll
                for (int nf = 0; nf < 4; nf++) {
                    uint32_t bo = bbase + stb + (uint32_t)(nf * 8 * LDA * 2) + kb;
                    ldsm2(bh[nf], bo + 2 * TILEB);
                    ldsm2(bl[nf], bo + 3 * TILEB);
                }
#pragma unroll
                for (int mf = 0; mf < 4; mf++) {
                    uint32_t ao = abase + stb + (uint32_t)(mf * 16 * LDA * 2) + kb;
                    uint32_t ah[4], al[4];
                    ldsm4(ah, ao);
#pragma unroll
                    for (int nf = 0; nf < 4; nf++) mma16816(acc[mf][nf], ah, bh[nf]);
#pragma unroll
                    for (int nf = 0; nf < 4; nf++) mma16816(acc[mf][nf], ah, bl[nf]);
                    ldsm4(al, ao + TILEB);
#pragma unroll
                    for (int nf = 0; nf < 4; nf++) mma16816(acc[mf][nf], al, bh[nf]);
                }
            }
            NBAR(1, 256);
        }

        // spill accumulators to smem exchange buffer (overlays stage bufs)
        {
            int r0 = wm * 64 + (lane >> 2);
            int c0 = wn * 32 + 2 * (lane & 3);
#pragma unroll
            for (int mf = 0; mf < 4; mf++)
#pragma unroll
                for (int nf = 0; nf < 4; nf++) {
                    int r = r0 + mf * 16, c = c0 + nf * 8;
                    *(float2*)&ex[r * EXLD + c] =
                        make_float2(acc[mf][nf][0], acc[mf][nf][1]);
                    *(float2*)&ex[(r + 8) * EXLD + c] =
                        make_float2(acc[mf][nf][2], acc[mf][nf][3]);
                }
        }
        __syncthreads();   // join with decode group; GEMM warps done
    } else {
        // ================= Decode group (warps 8-15), phases 0-3 ==========
        const int dtid = tid - 256;
        const int tx = dtid & 15;
        const int ty = dtid >> 4;
        uint2* pair_s = (uint2*)(smem + SM_PAIR);  // [128][16]
        const char* wbase = (const char*)g_Wdecb + (size_t)(d0 + tx * 8) * 2;
        float c[8][8];
#pragma unroll
        for (int i = 0; i < 8; i++)
#pragma unroll
            for (int j = 0; j < 8; j++) c[i][j] = 0.f;

        for (int ph = 0; ph < 4; ph++) {
            if (ph > 0) NBAR(2, 256);
#pragma unroll
            for (int q = 0; q < 8; q++) {
                int e = dtid * 8 + q;
                int t = e >> 4, k = e & 15;
                int gi = (n0 + t) * KTOP + ph * 16 + k;
                int id = lat_idx[gi];
                float a = (lat_acts[gi] + post_enc[id]) * pes[id];
                pair_s[t * 16 + k] = make_uint2((uint32_t)id << 11,
                                                __float_as_uint(a));
            }
            NBAR(2, 256);
            for (int k = 0; k < 16; k++) {
#pragma unroll
                for (int i = 0; i < 8; i++) {
                    int t = ty * 8 + i;
                    uint2 p = pair_s[t * 16 + k];
                    float a = __uint_as_float(p.y);
                    uint4 u = __ldg((const uint4*)(wbase + p.x));
                    c[i][0] += a * bf_lo(u.x); c[i][1] += a * bf_hi(u.x);
                    c[i][2] += a * bf_lo(u.y); c[i][3] += a * bf_hi(u.y);
                    c[i][4] += a * bf_lo(u.z); c[i][5] += a * bf_hi(u.z);
                    c[i][6] += a * bf_lo(u.w); c[i][7] += a * bf_hi(u.w);
                }
            }
        }
        __syncthreads();   // join: GEMM skip results now in ex

        // ---- epilogue: skip + decode + b_dec -> out, err partial --------
        float err = 0.f;
#pragma unroll
        for (int i = 0; i < 8; i++) {
            int t = ty * 8 + i;
            int n = n0 + t;
#pragma unroll
            for (int j = 0; j < 8; j += 4) {
                int d = d0 + tx * 8 + j;
                float4 bd = *(const float4*)&b_dec[d];
                float4 yv = *(const float4*)&y[(size_t)n * DIM + d];
                float4 sv = *(const float4*)&ex[t * EXLD + tx * 8 + j];
                float4 o;
                o.x = c[i][j + 0] + sv.x + bd.x;
                o.y = c[i][j + 1] + sv.y + bd.y;
                o.z = c[i][j + 2] + sv.z + bd.z;
                o.w = c[i][j + 3] + sv.w + bd.w;
                *(float4*)&out[(size_t)n * DIM + d] = o;
                float e0 = yv.x - o.x, e1 = yv.y - o.y;
                float e2 = yv.z - o.z, e3 = yv.w - o.w;
                err += e0 * e0 + e1 * e1 + e2 * e2 + e3 * e3;
            }
        }

        float* red = (float*)(smem + SM_RED);
        int* flag = (int*)(red + 8);
#pragma unroll
        for (int off = 16; off > 0; off >>= 1)
            err += __shfl_down_sync(0xFFFFFFFFu, err, off);
        if ((dtid & 31) == 0) red[dtid >> 5] = err;
        NBAR(2, 256);
        if (dtid == 0) {
            float s = 0.f;
#pragma unroll
            for (int q = 0; q < 8; q++) s += red[q];
            g_err_part[blockIdx.y * gridDim.x + blockIdx.x] = s;
            __threadfence();
            int r = atomicAdd(&g_done, 1);
            *flag = (r == (int)(gridDim.x * gridDim.y) - 1) ? 1 : 0;
        }
        NBAR(2, 256);

        // ---- last CTA: fvu from g_colsum (coalesced) --------------------
        if (*flag) {
            if (dtid == 0) __threadfence();   // acquire side
            NBAR(2, 256);
            float csq = 0.f;
#pragma unroll
            for (int q = 0; q < 4; q++) {
                float cs = g_colsum[dtid + q * 256];
                csq += cs * cs;
            }
            float s2 = (dtid < 256) ? g_s2_part[dtid] : 0.f;
            float er = g_err_part[dtid];
#pragma unroll
            for (int off = 16; off > 0; off >>= 1) {
                csq += __shfl_down_sync(0xFFFFFFFFu, csq, off);
                s2  += __shfl_down_sync(0xFFFFFFFFu, s2,  off);
                er  += __shfl_down_sync(0xFFFFFFFFu, er,  off);
            }
            float* r3 = red + 12;
            if ((dtid & 31) == 0) {
                r3[dtid >> 5]      = csq;
                r3[8 + (dtid >> 5)]  = s2;
                r3[16 + (dtid >> 5)] = er;
            }
            NBAR(2, 256);
            if (dtid == 0) {
                float a = 0.f, b = 0.f, e = 0.f;
#pragma unroll
                for (int q = 0; q < 8; q++) {
                    a += r3[q]; b += r3[8 + q]; e += r3[16 + q];
                }
                float tv = b - a / (float)NTOK;
                out[fvu_idx] = e / tv;
                g_done = 0;      // reset for next graph replay
            }
        }
    }
}

extern "C" void kernel_launch(void* const* d_in, const int* in_sizes, int n_in,
                              void* d_out, int out_size)
{
    const float* x        = (const float*)d_in[0];
    const float* y        = (const float*)d_in[1];
    const float* lat_acts = (const float*)d_in[2];
    const int*   lat_idx  = (const int*)  d_in[3];
    const float* W_dec    = (const float*)d_in[4];
    const float* b_dec    = (const float*)d_in[5];
    const float* post_enc = (const float*)d_in[6];
    const float* pes      = (const float*)d_in[7];
    const float* W_skip   = (const float*)d_in[8];
    float* out = (float*)d_out;

    cudaFuncSetAttribute(fused_kernel,
                         cudaFuncAttributeMaxDynamicSharedMemorySize, SMEM_DYN);

    prep_kernel<<<1280, 256>>>(x, y, W_skip, W_dec);
    reduce_colsum_kernel<<<32, 256>>>();
    fused_kernel<<<dim3(8, 32), 512, SMEM_DYN>>>(
        y, lat_acts, lat_idx, b_dec, post_enc, pes, out, out_size - 1);
}